// round 1
// baseline (speedup 1.0000x reference)
#include <cuda_runtime.h>

// Problem constants (fixed for this problem instance)
#define NN   131072
#define KT   27
#define CH   32
#define EPSV 1e-5f

// Scratch (device globals — no allocations allowed in kernel_launch)
__device__ float g_acc[NN * CH];        // 16 MB fp32 accumulator
__device__ float g_stats[2 * CH];       // [0:32) channel sums, [32:64) sums of squares

// ---------------------------------------------------------------------------
// f32x2 helpers (packed fp32 pairs; fma.rn.f32x2 is sm_100+ PTX)
// ---------------------------------------------------------------------------
__device__ __forceinline__ unsigned long long dup2(float x) {
    unsigned long long r;
    asm("mov.b64 %0, {%1, %1};" : "=l"(r) : "f"(x));
    return r;
}
__device__ __forceinline__ void ffma2(unsigned long long& d,
                                      unsigned long long a,
                                      unsigned long long b) {
    asm("fma.rn.f32x2 %0, %1, %2, %0;" : "+l"(d) : "l"(a), "l"(b));
}
union F2U { unsigned long long u; float2 f; };

// ---------------------------------------------------------------------------
// K0: zero the accumulator + stats (runs every launch: graph-replay safe)
// ---------------------------------------------------------------------------
__global__ void __launch_bounds__(256) zero_kernel() {
    int idx = blockIdx.x * 256 + threadIdx.x;            // float4 index
    ((float4*)g_acc)[idx] = make_float4(0.f, 0.f, 0.f, 0.f);
    if (blockIdx.x == 0 && threadIdx.x < 2 * CH) g_stats[threadIdx.x] = 0.f;
}

// ---------------------------------------------------------------------------
// K1: sparse transposed conv: for tap k, contrib = data_tile @ W[k], then
//     red.global.add.v4.f32 scatter into g_acc[neigh[n][k]].
// Block: 128 threads, 256-node tile, one tap (blockIdx.y).
// Thread: 8 nodes x 8 couts, accumulated as 8x4 f32x2 pairs.
// ---------------------------------------------------------------------------
__global__ void __launch_bounds__(128) scatter_gemm_kernel(
        const float* __restrict__ data,
        const float* __restrict__ weight,
        const int*   __restrict__ neigh) {
    __shared__ float sT[CH][260];      // data transposed [ci][node], pad to 260 (16B-aligned rows)
    __shared__ float sW[CH][CH];       // W[k] : [ci][cout]

    const int tid   = threadIdx.x;
    const int k     = blockIdx.y;
    const int gbase = blockIdx.x * 256;

    // --- stage data tile, transposed ---
    const float4* df4 = (const float4*)(data + (size_t)gbase * CH);
    #pragma unroll
    for (int i = 0; i < 16; i++) {
        int t = tid + i * 128;                 // 0..2047  (= node*8 + c4)
        float4 v = df4[t];
        int node = t >> 3;
        int c = (t & 7) * 4;
        sT[c + 0][node] = v.x;
        sT[c + 1][node] = v.y;
        sT[c + 2][node] = v.z;
        sT[c + 3][node] = v.w;
    }
    // --- stage W[k] ---
    const float* wk = weight + k * (CH * CH);
    #pragma unroll
    for (int i = 0; i < 8; i++)
        ((float*)sW)[tid + i * 128] = wk[tid + i * 128];
    __syncthreads();

    const int o0 = (tid & 3) * 8;        // cout group
    const int n0 = (tid >> 2) * 8;       // local node group

    unsigned long long acc[8][4];
    #pragma unroll
    for (int j = 0; j < 8; j++) {
        acc[j][0] = 0ull; acc[j][1] = 0ull; acc[j][2] = 0ull; acc[j][3] = 0ull;
    }

    #pragma unroll 4
    for (int ci = 0; ci < CH; ci++) {
        float4 d0 = *(const float4*)&sT[ci][n0];
        float4 d1 = *(const float4*)&sT[ci][n0 + 4];
        ulonglong2 w0 = *(const ulonglong2*)&sW[ci][o0];      // couts o0..o0+3 as 2 pairs
        ulonglong2 w1 = *(const ulonglong2*)&sW[ci][o0 + 4];  // couts o0+4..o0+7
        unsigned long long dd[8];
        dd[0] = dup2(d0.x); dd[1] = dup2(d0.y); dd[2] = dup2(d0.z); dd[3] = dup2(d0.w);
        dd[4] = dup2(d1.x); dd[5] = dup2(d1.y); dd[6] = dup2(d1.z); dd[7] = dup2(d1.w);
        #pragma unroll
        for (int j = 0; j < 8; j++) {
            ffma2(acc[j][0], dd[j], w0.x);
            ffma2(acc[j][1], dd[j], w0.y);
            ffma2(acc[j][2], dd[j], w1.x);
            ffma2(acc[j][3], dd[j], w1.y);
        }
    }

    // --- vectorized scatter-add into the accumulator ---
    #pragma unroll
    for (int j = 0; j < 8; j++) {
        int n   = gbase + n0 + j;
        int tgt = neigh[n * KT + k];
        float* dst = g_acc + (size_t)tgt * CH + o0;
        F2U a0, a1, a2, a3;
        a0.u = acc[j][0]; a1.u = acc[j][1]; a2.u = acc[j][2]; a3.u = acc[j][3];
        asm volatile("red.global.add.v4.f32 [%0], {%1,%2,%3,%4};" ::
                     "l"(dst), "f"(a0.f.x), "f"(a0.f.y), "f"(a1.f.x), "f"(a1.f.y)
                     : "memory");
        asm volatile("red.global.add.v4.f32 [%0], {%1,%2,%3,%4};" ::
                     "l"(dst + 4), "f"(a2.f.x), "f"(a2.f.y), "f"(a3.f.x), "f"(a3.f.y)
                     : "memory");
    }
}

// ---------------------------------------------------------------------------
// K2: per-channel sum and sum-of-squares over the N dimension
// grid 512 x 256 threads, each block covers 2048 float4s
// ---------------------------------------------------------------------------
__global__ void __launch_bounds__(256) stats_kernel() {
    __shared__ float ssum[CH], ssq[CH];
    int tid = threadIdx.x;
    if (tid < CH) { ssum[tid] = 0.f; ssq[tid] = 0.f; }
    __syncthreads();

    const float4* af4 = (const float4*)g_acc;
    int base = blockIdx.x * 2048 + tid;
    float s0 = 0, s1 = 0, s2 = 0, s3 = 0;
    float q0 = 0, q1 = 0, q2 = 0, q3 = 0;
    #pragma unroll
    for (int i = 0; i < 8; i++) {
        float4 v = af4[base + i * 256];
        s0 += v.x; s1 += v.y; s2 += v.z; s3 += v.w;
        q0 += v.x * v.x; q1 += v.y * v.y; q2 += v.z * v.z; q3 += v.w * v.w;
    }
    int c0 = (tid * 4) & 31;
    atomicAdd(&ssum[c0 + 0], s0); atomicAdd(&ssum[c0 + 1], s1);
    atomicAdd(&ssum[c0 + 2], s2); atomicAdd(&ssum[c0 + 3], s3);
    atomicAdd(&ssq[c0 + 0], q0);  atomicAdd(&ssq[c0 + 1], q1);
    atomicAdd(&ssq[c0 + 2], q2);  atomicAdd(&ssq[c0 + 3], q3);
    __syncthreads();
    if (tid < CH) {
        atomicAdd(&g_stats[tid], ssum[tid]);
        atomicAdd(&g_stats[CH + tid], ssq[tid]);
    }
}

// ---------------------------------------------------------------------------
// K3: BatchNorm (batch stats) + ReLU, write d_out
// ---------------------------------------------------------------------------
__global__ void __launch_bounds__(256) apply_kernel(const float* __restrict__ gamma,
                                                    const float* __restrict__ beta,
                                                    float* __restrict__ out) {
    int idx = blockIdx.x * 256 + threadIdx.x;    // float4 index
    int c0  = (threadIdx.x * 4) & 31;
    const float invN = 1.0f / (float)NN;
    float4 v = ((const float4*)g_acc)[idx];
    float vv[4] = { v.x, v.y, v.z, v.w };
    float r[4];
    #pragma unroll
    for (int m = 0; m < 4; m++) {
        int c = c0 + m;
        float mean = g_stats[c] * invN;
        float var  = g_stats[CH + c] * invN - mean * mean;
        float sc   = gamma[c] * rsqrtf(var + EPSV);
        float sh   = beta[c] - mean * sc;
        r[m] = fmaxf(vv[m] * sc + sh, 0.f);
    }
    ((float4*)out)[idx] = make_float4(r[0], r[1], r[2], r[3]);
}

// ---------------------------------------------------------------------------
extern "C" void kernel_launch(void* const* d_in, const int* in_sizes, int n_in,
                              void* d_out, int out_size) {
    const float* data   = (const float*)d_in[0];
    const float* weight = (const float*)d_in[1];
    const float* gamma  = (const float*)d_in[2];
    const float* beta   = (const float*)d_in[3];
    const int*   neigh  = (const int*)d_in[4];
    float* out = (float*)d_out;

    zero_kernel<<<(NN * CH / 4) / 256, 256>>>();
    dim3 grid(NN / 256, KT);
    scatter_gemm_kernel<<<grid, 128>>>(data, weight, neigh);
    stats_kernel<<<512, 256>>>();
    apply_kernel<<<(NN * CH / 4) / 256, 256>>>(gamma, beta, out);
}

// round 4
// speedup vs baseline: 1.8357x; 1.8357x over previous
#include <cuda_runtime.h>
#include <cuda_bf16.h>

// ---------------------------------------------------------------- constants
#define NN   131072
#define KT   27
#define CH   32
#define EPSV 1e-5f
#define NTILES 1024            // NN / 128

// ---------------------------------------------------------------- scratch
__device__ __align__(16) float g_acc[NN * CH];     // 16 MB accumulator
__device__ float g_stats[2 * CH];
// W in mma.sync B-fragment layout: u32 idx = (((tap*2+h)*2+q)*2+half)*128 + lane*4 + i
__device__ __align__(16) unsigned g_wfrag[KT * 1024];

// ---------------------------------------------------------------- helpers
__device__ __forceinline__ unsigned pk(__nv_bfloat16 a, __nv_bfloat16 b) {
    return (unsigned)__bfloat16_as_ushort(a) | ((unsigned)__bfloat16_as_ushort(b) << 16);
}
__device__ __forceinline__ void split2(float x, float y, unsigned& hi, unsigned& lo) {
    __nv_bfloat16 hx = __float2bfloat16(x), hy = __float2bfloat16(y);
    hi = pk(hx, hy);
    lo = pk(__float2bfloat16(x - __bfloat162float(hx)),
            __float2bfloat16(y - __bfloat162float(hy)));
}
__device__ __forceinline__ void mma16816(float* d, const unsigned* a, const unsigned* b) {
    asm volatile(
        "mma.sync.aligned.m16n8k16.row.col.f32.bf16.bf16.f32 "
        "{%0,%1,%2,%3}, {%4,%5,%6,%7}, {%8,%9}, {%0,%1,%2,%3};"
        : "+f"(d[0]), "+f"(d[1]), "+f"(d[2]), "+f"(d[3])
        : "r"(a[0]), "r"(a[1]), "r"(a[2]), "r"(a[3]), "r"(b[0]), "r"(b[1]));
}

// ---------------------------------------------------------------- K0: zero
__global__ void __launch_bounds__(256) zero_kernel() {
    int idx = blockIdx.x * 256 + threadIdx.x;
    ((float4*)g_acc)[idx] = make_float4(0.f, 0.f, 0.f, 0.f);
    if (blockIdx.x == 0 && threadIdx.x < 2 * CH) g_stats[threadIdx.x] = 0.f;
}

// ---------------------------------------------------------------- K1: W -> B-fragments
// B frag (m16n8k16, col): b0 = {B[2*(l%4)][l/4], B[2*(l%4)+1][l/4]}, b1 = +8 rows.
// Here B rows = cin (k), cols = cout (n); W stored [tap][cin][cout].
__global__ void __launch_bounds__(256) prep_w_kernel(const float* __restrict__ w) {
    int idx = blockIdx.x * 256 + threadIdx.x;          // 0 .. 27648-1
    int i    = idx & 3;
    int lane = (idx >> 2) & 31;
    int half = (idx >> 7) & 1;
    int q    = (idx >> 8) & 1;
    int h    = (idx >> 9) & 1;
    int tap  = idx >> 10;
    int c    = half * 2 + (i >> 1);
    int breg = i & 1;
    int n    = c * 8 + (lane >> 2);
    int kk   = q * 16 + breg * 8 + 2 * (lane & 3);
    float f0 = w[tap * 1024 + kk * 32 + n];
    float f1 = w[tap * 1024 + (kk + 1) * 32 + n];
    unsigned v;
    if (h == 0) {
        v = pk(__float2bfloat16(f0), __float2bfloat16(f1));
    } else {
        __nv_bfloat16 h0 = __float2bfloat16(f0), h1 = __float2bfloat16(f1);
        v = pk(__float2bfloat16(f0 - __bfloat162float(h0)),
               __float2bfloat16(f1 - __bfloat162float(h1)));
    }
    g_wfrag[idx] = v;
}

// ---------------------------------------------------------------- K2: main
// 1024 blocks x 128 threads. Block = 128-node tile. Warp w owns rows [w*32, w*32+32).
// Per tap: 48 HMMA (hi/lo 3-term) -> smem transpose (double buffered) ->
// coalesced red.global.add.v4 (8 lanes = one 128B output row).
__global__ void __launch_bounds__(128) deconv_mma_kernel(
        const float* __restrict__ data, const int* __restrict__ neigh) {
    extern __shared__ float smem[];
    float* sStage = smem;                         // [2][128*36] floats = 36864 B
    int*   sNeigh = (int*)(smem + 2 * 128 * 36);  // [128*27] = 13824 B

    const int tid = threadIdx.x;
    const int wid = tid >> 5;
    const int lid = tid & 31;
    const int gbase = blockIdx.x * 128;

    // neigh rows -> smem (coalesced)
    for (int i = tid; i < 128 * KT; i += 128)
        sNeigh[i] = neigh[gbase * KT + i];

    // ---- A fragments straight from global, hi/lo bf16 split ----
    const int R0 = gbase + wid * 32 + (lid >> 2);
    const int j2 = (lid & 3) * 2;
    float2 v[4][4];
    #pragma unroll
    for (int ri = 0; ri < 4; ri++)
        #pragma unroll
        for (int ci = 0; ci < 4; ci++)
            v[ri][ci] = *(const float2*)(data + (size_t)(R0 + ri * 8) * CH + ci * 8 + j2);

    unsigned AH[2][2][4], AL[2][2][4];
    #pragma unroll
    for (int M = 0; M < 2; M++)
        #pragma unroll
        for (int Q = 0; Q < 2; Q++) {
            split2(v[2*M][2*Q].x,   v[2*M][2*Q].y,   AH[M][Q][0], AL[M][Q][0]);
            split2(v[2*M+1][2*Q].x, v[2*M+1][2*Q].y, AH[M][Q][1], AL[M][Q][1]);
            split2(v[2*M][2*Q+1].x, v[2*M][2*Q+1].y, AH[M][Q][2], AL[M][Q][2]);
            split2(v[2*M+1][2*Q+1].x, v[2*M+1][2*Q+1].y, AH[M][Q][3], AL[M][Q][3]);
        }
    __syncthreads();

    const uint4* wf = (const uint4*)g_wfrag;

    #pragma unroll 1
    for (int t = 0; t < KT; t++) {
        // ---- B fragments: 8 coalesced LDG.128, L1/L2-resident ----
        unsigned B[2][2][4][2];                    // [h][q][c][reg]
        #pragma unroll
        for (int h = 0; h < 2; h++)
            #pragma unroll
            for (int q = 0; q < 2; q++)
                #pragma unroll
                for (int half = 0; half < 2; half++) {
                    uint4 u = wf[(t * 8 + h * 4 + q * 2 + half) * 32 + lid];
                    B[h][q][half*2][0]   = u.x;  B[h][q][half*2][1]   = u.y;
                    B[h][q][half*2+1][0] = u.z;  B[h][q][half*2+1][1] = u.w;
                }

        // ---- 48 HMMA: D = Ah*Wh + Ah*Wl + Al*Wh ----
        float D[2][4][4];
        #pragma unroll
        for (int M = 0; M < 2; M++)
            #pragma unroll
            for (int c = 0; c < 4; c++) {
                #pragma unroll
                for (int r = 0; r < 4; r++) D[M][c][r] = 0.f;
                #pragma unroll
                for (int Q = 0; Q < 2; Q++) {
                    mma16816(D[M][c], AH[M][Q], B[0][Q][c]);
                    mma16816(D[M][c], AH[M][Q], B[1][Q][c]);
                    mma16816(D[M][c], AL[M][Q], B[0][Q][c]);
                }
            }

        // ---- stage to smem (double buffer), 36-word row stride ----
        float* S = sStage + (t & 1) * (128 * 36);
        const int Lr = wid * 32 + (lid >> 2);
        #pragma unroll
        for (int M = 0; M < 2; M++)
            #pragma unroll
            for (int c = 0; c < 4; c++) {
                int col = c * 8 + j2;
                *(float2*)&S[(Lr + M*16)     * 36 + col] = make_float2(D[M][c][0], D[M][c][1]);
                *(float2*)&S[(Lr + M*16 + 8) * 36 + col] = make_float2(D[M][c][2], D[M][c][3]);
            }
        __syncthreads();

        // ---- coalesced scatter: 8 lanes cover one output row (128B) ----
        #pragma unroll
        for (int i = 0; i < 8; i++) {
            int flat = i * 128 + tid;
            int rr = flat >> 3, cl = flat & 7;
            int tgt = sNeigh[rr * KT + t];
            float4 val = *(float4*)&S[rr * 36 + cl * 4];
            float* dst = g_acc + (size_t)tgt * CH + cl * 4;
            asm volatile("red.global.add.v4.f32 [%0], {%1,%2,%3,%4};"
                         :: "l"(dst), "f"(val.x), "f"(val.y), "f"(val.z), "f"(val.w)
                         : "memory");
        }
        // no trailing bar: double buffer + next tap's bar provides the ordering
    }
}

// ---------------------------------------------------------------- K3: stats
__global__ void __launch_bounds__(256) stats_kernel() {
    __shared__ float ssum[CH], ssq[CH];
    int tid = threadIdx.x;
    if (tid < CH) { ssum[tid] = 0.f; ssq[tid] = 0.f; }
    __syncthreads();
    const float4* af4 = (const float4*)g_acc;
    int base = blockIdx.x * 2048 + tid;
    float s0=0,s1=0,s2=0,s3=0,q0=0,q1=0,q2=0,q3=0;
    #pragma unroll
    for (int i = 0; i < 8; i++) {
        float4 v = af4[base + i * 256];
        s0 += v.x; s1 += v.y; s2 += v.z; s3 += v.w;
        q0 += v.x*v.x; q1 += v.y*v.y; q2 += v.z*v.z; q3 += v.w*v.w;
    }
    int c0 = (tid * 4) & 31;
    atomicAdd(&ssum[c0+0], s0); atomicAdd(&ssum[c0+1], s1);
    atomicAdd(&ssum[c0+2], s2); atomicAdd(&ssum[c0+3], s3);
    atomicAdd(&ssq[c0+0], q0);  atomicAdd(&ssq[c0+1], q1);
    atomicAdd(&ssq[c0+2], q2);  atomicAdd(&ssq[c0+3], q3);
    __syncthreads();
    if (tid < CH) {
        atomicAdd(&g_stats[tid], ssum[tid]);
        atomicAdd(&g_stats[CH + tid], ssq[tid]);
    }
}

// ---------------------------------------------------------------- K4: BN+ReLU
__global__ void __launch_bounds__(256) apply_kernel(const float* __restrict__ gamma,
                                                    const float* __restrict__ beta,
                                                    float* __restrict__ out) {
    int idx = blockIdx.x * 256 + threadIdx.x;
    int c0  = (threadIdx.x * 4) & 31;
    const float invN = 1.0f / (float)NN;
    float4 v = ((const float4*)g_acc)[idx];
    float vv[4] = { v.x, v.y, v.z, v.w };
    float r[4];
    #pragma unroll
    for (int m = 0; m < 4; m++) {
        int c = c0 + m;
        float mean = g_stats[c] * invN;
        float var  = g_stats[CH + c] * invN - mean * mean;
        float sc   = gamma[c] * rsqrtf(var + EPSV);
        float sh   = beta[c] - mean * sc;
        r[m] = fmaxf(vv[m] * sc + sh, 0.f);
    }
    ((float4*)out)[idx] = make_float4(r[0], r[1], r[2], r[3]);
}

// ----------------------------------------------------------------
extern "C" void kernel_launch(void* const* d_in, const int* in_sizes, int n_in,
                              void* d_out, int out_size) {
    const float* data   = (const float*)d_in[0];
    const float* weight = (const float*)d_in[1];
    const float* gamma  = (const float*)d_in[2];
    const float* beta   = (const float*)d_in[3];
    const int*   neigh  = (const int*)d_in[4];
    float* out = (float*)d_out;

    const int smem_bytes = 2 * 128 * 36 * 4 + 128 * KT * 4;   // 50688
    cudaFuncSetAttribute(deconv_mma_kernel,
                         cudaFuncAttributeMaxDynamicSharedMemorySize, smem_bytes);

    zero_kernel<<<(NN * CH / 4) / 256, 256>>>();
    prep_w_kernel<<<(KT * 1024) / 256, 256>>>(weight);
    deconv_mma_kernel<<<NTILES, 128, smem_bytes>>>(data, neigh);
    stats_kernel<<<512, 256>>>();
    apply_kernel<<<(NN * CH / 4) / 256, 256>>>(gamma, beta, out);
}

// round 5
// speedup vs baseline: 1.9351x; 1.0541x over previous
#include <cuda_runtime.h>
#include <cuda_bf16.h>

// ---------------------------------------------------------------- constants
#define NN   131072
#define KT   27
#define CH   32
#define EPSV 1e-5f
#define NTILES 1024            // NN / 128

// ---------------------------------------------------------------- scratch
__device__ __align__(16) float g_acc[NN * CH];     // 16 MB accumulator
__device__ float g_stats[2 * CH];
// W in mma.sync B-fragment layout: u32 idx = (((tap*2+h)*2+q)*2+half)*128 + lane*4 + i
__device__ __align__(16) unsigned g_wfrag[KT * 1024];

// ---------------------------------------------------------------- helpers
__device__ __forceinline__ unsigned pk(__nv_bfloat16 a, __nv_bfloat16 b) {
    return (unsigned)__bfloat16_as_ushort(a) | ((unsigned)__bfloat16_as_ushort(b) << 16);
}
__device__ __forceinline__ void split2(float x, float y, unsigned& hi, unsigned& lo) {
    __nv_bfloat16 hx = __float2bfloat16(x), hy = __float2bfloat16(y);
    hi = pk(hx, hy);
    lo = pk(__float2bfloat16(x - __bfloat162float(hx)),
            __float2bfloat16(y - __bfloat162float(hy)));
}
__device__ __forceinline__ void mma16816(float* d, const unsigned* a, const unsigned* b) {
    asm volatile(
        "mma.sync.aligned.m16n8k16.row.col.f32.bf16.bf16.f32 "
        "{%0,%1,%2,%3}, {%4,%5,%6,%7}, {%8,%9}, {%0,%1,%2,%3};"
        : "+f"(d[0]), "+f"(d[1]), "+f"(d[2]), "+f"(d[3])
        : "r"(a[0]), "r"(a[1]), "r"(a[2]), "r"(a[3]), "r"(b[0]), "r"(b[1]));
}

// ---------------------------------------------------------------- K0: init
// blocks [0,4096): zero g_acc (+stats); blocks [4096,4204): W -> B-fragment layout.
__global__ void __launch_bounds__(256) init_kernel(const float* __restrict__ w) {
    int b = blockIdx.x;
    int tid = threadIdx.x;
    if (b < 4096) {
        ((float4*)g_acc)[b * 256 + tid] = make_float4(0.f, 0.f, 0.f, 0.f);
        if (b == 0 && tid < 2 * CH) g_stats[tid] = 0.f;
        return;
    }
    int idx = (b - 4096) * 256 + tid;                  // 0 .. 27647
    int i    = idx & 3;
    int lane = (idx >> 2) & 31;
    int half = (idx >> 7) & 1;
    int q    = (idx >> 8) & 1;
    int h    = (idx >> 9) & 1;
    int tap  = idx >> 10;
    int c    = half * 2 + (i >> 1);
    int breg = i & 1;
    int n    = c * 8 + (lane >> 2);
    int kk   = q * 16 + breg * 8 + 2 * (lane & 3);
    float f0 = w[tap * 1024 + kk * 32 + n];
    float f1 = w[tap * 1024 + (kk + 1) * 32 + n];
    unsigned v;
    if (h == 0) {
        v = pk(__float2bfloat16(f0), __float2bfloat16(f1));
    } else {
        __nv_bfloat16 h0 = __float2bfloat16(f0), h1 = __float2bfloat16(f1);
        v = pk(__float2bfloat16(f0 - __bfloat162float(h0)),
               __float2bfloat16(f1 - __bfloat162float(h1)));
    }
    g_wfrag[idx] = v;
}

// ---------------------------------------------------------------- K1: main
// 1024 blocks x 128 threads. Block = 128-node tile. Warp w owns rows [w*32, w*32+32).
// Per tap: 48 HMMA (hi/lo 3-term) -> smem transpose (double buffered) ->
// coalesced red.global.add.v4 (8 lanes = one 128B output row).
__global__ void __launch_bounds__(128) deconv_mma_kernel(
        const float* __restrict__ data, const int* __restrict__ neigh) {
    extern __shared__ float smem[];
    float* sStage = smem;                         // [2][128*36] floats = 36864 B
    int*   sNeigh = (int*)(smem + 2 * 128 * 36);  // [128*27] = 13824 B

    const int tid = threadIdx.x;
    const int wid = tid >> 5;
    const int lid = tid & 31;
    const int gbase = blockIdx.x * 128;

    // neigh rows -> smem (coalesced)
    for (int i = tid; i < 128 * KT; i += 128)
        sNeigh[i] = neigh[gbase * KT + i];

    // ---- A fragments straight from global, hi/lo bf16 split ----
    const int R0 = gbase + wid * 32 + (lid >> 2);
    const int j2 = (lid & 3) * 2;
    float2 v[4][4];
    #pragma unroll
    for (int ri = 0; ri < 4; ri++)
        #pragma unroll
        for (int ci = 0; ci < 4; ci++)
            v[ri][ci] = *(const float2*)(data + (size_t)(R0 + ri * 8) * CH + ci * 8 + j2);

    unsigned AH[2][2][4], AL[2][2][4];
    #pragma unroll
    for (int M = 0; M < 2; M++)
        #pragma unroll
        for (int Q = 0; Q < 2; Q++) {
            split2(v[2*M][2*Q].x,   v[2*M][2*Q].y,   AH[M][Q][0], AL[M][Q][0]);
            split2(v[2*M+1][2*Q].x, v[2*M+1][2*Q].y, AH[M][Q][1], AL[M][Q][1]);
            split2(v[2*M][2*Q+1].x, v[2*M][2*Q+1].y, AH[M][Q][2], AL[M][Q][2]);
            split2(v[2*M+1][2*Q+1].x, v[2*M+1][2*Q+1].y, AH[M][Q][3], AL[M][Q][3]);
        }
    __syncthreads();

    const uint4* wf = (const uint4*)g_wfrag;

    #pragma unroll 1
    for (int t = 0; t < KT; t++) {
        // ---- B fragments: 8 coalesced LDG.128, L1/L2-resident ----
        unsigned B[2][2][4][2];                    // [h][q][c][reg]
        #pragma unroll
        for (int h = 0; h < 2; h++)
            #pragma unroll
            for (int q = 0; q < 2; q++)
                #pragma unroll
                for (int half = 0; half < 2; half++) {
                    uint4 u = wf[(t * 8 + h * 4 + q * 2 + half) * 32 + lid];
                    B[h][q][half*2][0]   = u.x;  B[h][q][half*2][1]   = u.y;
                    B[h][q][half*2+1][0] = u.z;  B[h][q][half*2+1][1] = u.w;
                }

        // ---- 48 HMMA: D = Ah*Wh + Ah*Wl + Al*Wh ----
        float D[2][4][4];
        #pragma unroll
        for (int M = 0; M < 2; M++)
            #pragma unroll
            for (int c = 0; c < 4; c++) {
                #pragma unroll
                for (int r = 0; r < 4; r++) D[M][c][r] = 0.f;
                #pragma unroll
                for (int Q = 0; Q < 2; Q++) {
                    mma16816(D[M][c], AH[M][Q], B[0][Q][c]);
                    mma16816(D[M][c], AH[M][Q], B[1][Q][c]);
                    mma16816(D[M][c], AL[M][Q], B[0][Q][c]);
                }
            }

        // ---- stage to smem (double buffer), 36-word row stride ----
        float* S = sStage + (t & 1) * (128 * 36);
        const int Lr = wid * 32 + (lid >> 2);
        #pragma unroll
        for (int M = 0; M < 2; M++)
            #pragma unroll
            for (int c = 0; c < 4; c++) {
                int col = c * 8 + j2;
                *(float2*)&S[(Lr + M*16)     * 36 + col] = make_float2(D[M][c][0], D[M][c][1]);
                *(float2*)&S[(Lr + M*16 + 8) * 36 + col] = make_float2(D[M][c][2], D[M][c][3]);
            }
        __syncthreads();

        // ---- coalesced scatter: 8 lanes cover one output row (128B) ----
        #pragma unroll
        for (int i = 0; i < 8; i++) {
            int flat = i * 128 + tid;
            int rr = flat >> 3, cl = flat & 7;
            int tgt = sNeigh[rr * KT + t];
            float4 val = *(float4*)&S[rr * 36 + cl * 4];
            float* dst = g_acc + (size_t)tgt * CH + cl * 4;
            asm volatile("red.global.add.v4.f32 [%0], {%1,%2,%3,%4};"
                         :: "l"(dst), "f"(val.x), "f"(val.y), "f"(val.z), "f"(val.w)
                         : "memory");
        }
        // no trailing bar: double buffer + next tap's bar provides the ordering
    }
}

// ---------------------------------------------------------------- K2: stats
// 256 blocks x 256 thr; 16 float4 per thread in registers, shfl-xor reduce,
// 8 conflict-free smem atomics per warp, 64 global atomics per block.
__global__ void __launch_bounds__(256) stats_kernel() {
    __shared__ float ssum[CH], ssq[CH];
    const int tid = threadIdx.x;
    const int lid = tid & 31;
    if (tid < CH) { ssum[tid] = 0.f; ssq[tid] = 0.f; }
    __syncthreads();

    const float4* af4 = (const float4*)g_acc;
    const int gid = blockIdx.x * 256 + tid;            // [0, 65536)
    float s[4] = {0, 0, 0, 0}, q[4] = {0, 0, 0, 0};
    #pragma unroll
    for (int i = 0; i < 16; i++) {
        float4 v = af4[gid + i * 65536];
        s[0] += v.x; s[1] += v.y; s[2] += v.z; s[3] += v.w;
        q[0] += v.x * v.x; q[1] += v.y * v.y;
        q[2] += v.z * v.z; q[3] += v.w * v.w;
    }
    // lanes l, l^8, l^16, l^24 share the same channel group
    #pragma unroll
    for (int m = 0; m < 4; m++) {
        s[m] += __shfl_xor_sync(0xFFFFFFFF, s[m], 8);
        s[m] += __shfl_xor_sync(0xFFFFFFFF, s[m], 16);
        q[m] += __shfl_xor_sync(0xFFFFFFFF, q[m], 8);
        q[m] += __shfl_xor_sync(0xFFFFFFFF, q[m], 16);
    }
    if (lid < 8) {
        int c0 = lid * 4;
        #pragma unroll
        for (int m = 0; m < 4; m++) {
            atomicAdd(&ssum[c0 + m], s[m]);
            atomicAdd(&ssq[c0 + m], q[m]);
        }
    }
    __syncthreads();
    if (tid < CH) {
        atomicAdd(&g_stats[tid], ssum[tid]);
        atomicAdd(&g_stats[CH + tid], ssq[tid]);
    }
}

// ---------------------------------------------------------------- K3: BN+ReLU
__global__ void __launch_bounds__(256) apply_kernel(const float* __restrict__ gamma,
                                                    const float* __restrict__ beta,
                                                    float* __restrict__ out) {
    const int gid = blockIdx.x * 256 + threadIdx.x;    // [0, 524288)
    const int c0  = (gid & 7) * 4;
    const float invN = 1.0f / (float)NN;
    float sc[4], sh[4];
    #pragma unroll
    for (int m = 0; m < 4; m++) {
        int c = c0 + m;
        float mean = g_stats[c] * invN;
        float var  = g_stats[CH + c] * invN - mean * mean;
        sc[m] = gamma[c] * rsqrtf(var + EPSV);
        sh[m] = beta[c] - mean * sc[m];
    }
    #pragma unroll
    for (int i = 0; i < 2; i++) {
        int idx = gid + i * 524288;
        float4 v = ((const float4*)g_acc)[idx];
        float4 r;
        r.x = fmaxf(v.x * sc[0] + sh[0], 0.f);
        r.y = fmaxf(v.y * sc[1] + sh[1], 0.f);
        r.z = fmaxf(v.z * sc[2] + sh[2], 0.f);
        r.w = fmaxf(v.w * sc[3] + sh[3], 0.f);
        ((float4*)out)[idx] = r;
    }
}

// ----------------------------------------------------------------
extern "C" void kernel_launch(void* const* d_in, const int* in_sizes, int n_in,
                              void* d_out, int out_size) {
    const float* data   = (const float*)d_in[0];
    const float* weight = (const float*)d_in[1];
    const float* gamma  = (const float*)d_in[2];
    const float* beta   = (const float*)d_in[3];
    const int*   neigh  = (const int*)d_in[4];
    float* out = (float*)d_out;

    const int smem_bytes = 2 * 128 * 36 * 4 + 128 * KT * 4;   // 50688
    cudaFuncSetAttribute(deconv_mma_kernel,
                         cudaFuncAttributeMaxDynamicSharedMemorySize, smem_bytes);

    init_kernel<<<4096 + 108, 256>>>(weight);
    deconv_mma_kernel<<<NTILES, 128, smem_bytes>>>(data, neigh);
    stats_kernel<<<256, 256>>>();
    apply_kernel<<<2048, 256>>>(gamma, beta, out);
}